// round 7
// baseline (speedup 1.0000x reference)
#include <cuda_runtime.h>
#include <cstdint>
#include <cstddef>

#define BATCH 8192
#define NREC  1024
#define HID   2048

#define BK 32
#define SA 36       // A smem row stride (floats)
#define SB 136      // tensor-B smem row stride (floats)
#define SF 36       // ffma-B smem row stride (floats)
#define A_TILE (128 * SA)    // 4608
#define B_TILE (BK * SB)     // 4352
#define F_TILE (BK * SF)     // 1152

// GEMM1 stage: A + Bre + Bim + Fre + Fim
#define ST1 (A_TILE + 2 * B_TILE + 2 * F_TILE)   // 15616 floats
#define SMEM1 (3 * ST1 * (int)sizeof(float))     // 187392
// GEMM2 stage: A + B + F
#define ST2 (A_TILE + B_TILE + F_TILE)           // 10112 floats
#define SMEM2 (3 * ST2 * (int)sizeof(float))     // 121344

extern __shared__ float smem[];

// prepped weights (rna-rounded, n-permuted within 32-col blocks, Cim negated); padded vs OOB tail reads
__device__ float g_B[2u * NREC * HID + 2048];
__device__ float g_C[2u * HID * NREC + 2048];

__device__ __forceinline__ uint32_t f2tf32(float x) {
    uint32_t r; asm("cvt.rna.tf32.f32 %0, %1;" : "=r"(r) : "f"(x)); return r;
}
__device__ __forceinline__ void mma8(float* d, const uint32_t* a, uint32_t b0, uint32_t b1) {
    asm volatile(
        "mma.sync.aligned.m16n8k8.row.col.f32.tf32.tf32.f32 "
        "{%0,%1,%2,%3}, {%4,%5,%6,%7}, {%8,%9}, {%0,%1,%2,%3};\n"
        : "+f"(d[0]), "+f"(d[1]), "+f"(d[2]), "+f"(d[3])
        : "r"(a[0]), "r"(a[1]), "r"(a[2]), "r"(a[3]), "r"(b0), "r"(b1));
}
__device__ __forceinline__ void cp16(float* s, const float* g) {
    uint32_t sa = (uint32_t)__cvta_generic_to_shared(s);
    asm volatile("cp.async.cg.shared.global [%0], [%1], 16;\n" :: "r"(sa), "l"(g));
}
__device__ __forceinline__ void cp_commit() { asm volatile("cp.async.commit_group;\n"); }
__device__ __forceinline__ void cp_wait0()  { asm volatile("cp.async.wait_group 0;\n"); }
__device__ __forceinline__ void cp_wait1()  { asm volatile("cp.async.wait_group 1;\n"); }

// ---- prep: rna-round + column permutation within each 32-col block (+negate Cim).
// stored col (base+p) holds source col (base + (p&3)*8 + (p>>2)).
// For TENSOR fragments this permutation makes LDS.128 deliver exactly the mma-b layout,
// and the accumulator for local col cl corresponds to TRUE col n0+cl (direct epilogue).
// For FFMA tiles (plain vector loads) stored col pl holds true col unperm(pl).
__global__ __launch_bounds__(256) void prep_all(
    const float* __restrict__ B0, const float* __restrict__ B1,
    const float* __restrict__ C0, const float* __restrict__ C1,
    float* __restrict__ Bp, float* __restrict__ Cp)
{
    const int idx = blockIdx.x * 256 + threadIdx.x;
    const int z = blockIdx.y;
    const float* src; float* dst; int sh; float sign = 1.f;
    if (z == 0)      { src = B0; dst = Bp;                      sh = 11; }
    else if (z == 1) { src = B1; dst = Bp + (size_t)NREC * HID; sh = 11; }
    else if (z == 2) { src = C0; dst = Cp;                      sh = 10; }
    else             { src = C1; dst = Cp + (size_t)HID * NREC; sh = 10; sign = -1.f; }
    const int N = 1 << sh;
    const int row = idx >> sh, l = idx & (N - 1);
    const int base = l & ~31, p = l & 31;
    const int sl = base + ((p & 3) * 8) + (p >> 2);
    dst[idx] = __uint_as_float(f2tf32(sign * src[((size_t)row << sh) + sl]));
}

// stored-local col p -> true col offset within its 32-block
__device__ __forceinline__ int unperm(int p) { return ((p & 3) * 8) + (p >> 2); }

// =============================================================================
// GEMM1: T = U @ {Bre',Bim'}; X = f(S,T).  Block: 128M x (128 tensor + 32 ffma) N
// =============================================================================
__global__ __launch_bounds__(256, 1) void lru_g1(
    const float* __restrict__ U,
    const float* __restrict__ Bp,
    const float* __restrict__ Sre, const float* __restrict__ Sim,
    const float* __restrict__ nu,  const float* __restrict__ theta,
    const float* __restrict__ gam,
    float* __restrict__ Xre, float* __restrict__ Xim)
{
    const int n0 = blockIdx.x * 160;     // HID
    const int m0 = blockIdx.y * 128;     // BATCH
    const bool nf_act = (n0 + 160 <= HID);
    const float* __restrict__ Bre = Bp;
    const float* __restrict__ Bim = Bp + (size_t)NREC * HID;

    const int tid = threadIdx.x, warp = tid >> 5, lane = tid & 31;
    const int g = lane >> 2, t = lane & 3;
    const int wm = (warp >> 2) * 64, wn = (warp & 3) * 32;
    const int fr0 = warp * 16, rg = lane >> 3, cg = lane & 7;

    float ar[4][4][4], ai[4][4][4];
    float accf[2][4][4];
    #pragma unroll
    for (int i = 0; i < 4; i++)
        #pragma unroll
        for (int j = 0; j < 4; j++) {
            #pragma unroll
            for (int r = 0; r < 4; r++) { ar[i][j][r] = 0.f; ai[i][j][r] = 0.f; }
            accf[0][i][j] = 0.f; accf[1][i][j] = 0.f;
        }

    auto loadStage = [&](int s, int k0) {
        float* a  = smem + s * ST1;
        float* br = a + A_TILE;
        float* bi = br + B_TILE;
        float* fr = bi + B_TILE;
        float* fi = fr + F_TILE;
        #pragma unroll
        for (int i = 0; i < 4; i++) {
            int c = tid + i * 256;
            int row = c >> 3, cc = (c & 7) * 4;
            cp16(a + row * SA + cc, U + (size_t)(m0 + row) * NREC + k0 + cc);
        }
        #pragma unroll
        for (int i = 0; i < 4; i++) {
            int c = tid + i * 256;
            int row = c >> 5, cc = (c & 31) * 4;
            size_t go = (size_t)(k0 + row) * HID + n0 + cc;
            cp16(br + row * SB + cc, Bre + go);
            cp16(bi + row * SB + cc, Bim + go);
        }
        if (nf_act) {
            int row = tid >> 3, cc = (tid & 7) * 4;
            size_t go = (size_t)(k0 + row) * HID + n0 + 128 + cc;
            cp16(fr + row * SF + cc, Bre + go);
            cp16(fi + row * SF + cc, Bim + go);
        }
    };

    const int NKT = NREC / BK;   // 32
    loadStage(0, 0); cp_commit();
    loadStage(1, BK); cp_commit();

    for (int kt = 0; kt < NKT; kt++) {
        if (kt + 2 < NKT) cp_wait1(); else cp_wait0();
        __syncthreads();
        if (kt + 2 < NKT) { loadStage((kt + 2) % 3, (kt + 2) * BK); cp_commit(); }

        const int s = kt % 3;
        const uint32_t* a  = (const uint32_t*)(smem + s * ST1);
        const uint32_t* br = a + A_TILE;
        const uint32_t* bi = br + B_TILE;
        const float* fA  = (const float*)a;
        const float* fFr = (const float*)(bi + B_TILE);
        const float* fFi = fFr + F_TILE;

        #pragma unroll
        for (int ks = 0; ks < 4; ks++) {
            const int kk = ks * 8;
            uint32_t af[4][4];
            #pragma unroll
            for (int i = 0; i < 4; i++) {
                int r = wm + i * 16 + g;
                af[i][0] = a[r * SA + kk + t];
                af[i][1] = a[(r + 8) * SA + kk + t];
                af[i][2] = a[r * SA + kk + t + 4];
                af[i][3] = a[(r + 8) * SA + kk + t + 4];
            }
            uint4 v0 = *(const uint4*)(br + (kk + t) * SB + wn + 4 * g);
            uint4 v1 = *(const uint4*)(br + (kk + t + 4) * SB + wn + 4 * g);
            uint4 w0 = *(const uint4*)(bi + (kk + t) * SB + wn + 4 * g);
            uint4 w1 = *(const uint4*)(bi + (kk + t + 4) * SB + wn + 4 * g);
            uint32_t b0[4] = {v0.x, v0.y, v0.z, v0.w};
            uint32_t b1[4] = {v1.x, v1.y, v1.z, v1.w};
            uint32_t c0[4] = {w0.x, w0.y, w0.z, w0.w};
            uint32_t c1[4] = {w1.x, w1.y, w1.z, w1.w};
            #pragma unroll
            for (int i = 0; i < 4; i++) {
                #pragma unroll
                for (int j = 0; j < 4; j++) {
                    mma8(ar[i][j], af[i], b0[j], b1[j]);
                    mma8(ai[i][j], af[i], c0[j], c1[j]);
                }
                // interleaved FFMA chunk: 16 chunks per ktile (8 per matrix), 4-k each
                {
                    const int chunk = ks * 4 + i;
                    const int mat = chunk >> 3, kc = chunk & 7;
                    const float* fF = mat ? fFi : fFr;
                    float av[4][4], bv[4][4];
                    #pragma unroll
                    for (int rr = 0; rr < 4; rr++) {
                        float4 q = *(const float4*)(fA + (fr0 + 4 * rg + rr) * SA + kc * 4);
                        av[rr][0] = q.x; av[rr][1] = q.y; av[rr][2] = q.z; av[rr][3] = q.w;
                    }
                    #pragma unroll
                    for (int k3 = 0; k3 < 4; k3++) {
                        float4 q = *(const float4*)(fF + (kc * 4 + k3) * SF + 4 * cg);
                        bv[k3][0] = q.x; bv[k3][1] = q.y; bv[k3][2] = q.z; bv[k3][3] = q.w;
                    }
                    float (*acf)[4] = accf[mat];
                    #pragma unroll
                    for (int k3 = 0; k3 < 4; k3++)
                        #pragma unroll
                        for (int rr = 0; rr < 4; rr++)
                            #pragma unroll
                            for (int cc = 0; cc < 4; cc++)
                                acf[rr][cc] += av[rr][k3] * bv[k3][cc];
                }
            }
        }
    }

    // tables indexed by TRUE column offset (0..159) relative to n0
    float* sLr = smem;
    float* sLi = smem + 160;
    float* sG  = smem + 320;
    if (tid < 160) {
        int h = n0 + tid;
        if (h < HID) {
            float e = expf(-expf(nu[h]));
            float th = theta[h];
            sLr[tid] = e * cosf(th);
            sLi[tid] = e * sinf(th);
            sG[tid]  = gam[h];
        }
    }
    __syncthreads();

    // tensor epilogue: accumulator local col cl IS true col n0+cl (direct, contiguous)
    #pragma unroll
    for (int i = 0; i < 4; i++) {
        int r0 = m0 + wm + i * 16 + g;
        #pragma unroll
        for (int j = 0; j < 4; j++) {
            int cl = wn + j * 8 + 2 * t;
            float lr0 = sLr[cl],     li0 = sLi[cl],     g0 = sG[cl];
            float lr1 = sLr[cl + 1], li1 = sLi[cl + 1], g1 = sG[cl + 1];
            #pragma unroll
            for (int rr = 0; rr < 2; rr++) {
                int r = r0 + rr * 8;
                size_t off = (size_t)r * HID + n0 + cl;
                float2 sre = *(const float2*)(Sre + off);
                float2 sim = *(const float2*)(Sim + off);
                float tr0 = ar[i][j][rr * 2 + 0], tr1 = ar[i][j][rr * 2 + 1];
                float ti0 = ai[i][j][rr * 2 + 0], ti1 = ai[i][j][rr * 2 + 1];
                float2 ore, oim;
                ore.x = sre.x * lr0 - sim.x * li0 + g0 * tr0;
                ore.y = sre.y * lr1 - sim.y * li1 + g1 * tr1;
                oim.x = sre.x * li0 + sim.x * lr0 + g0 * ti0;
                oim.y = sre.y * li1 + sim.y * lr1 + g1 * ti1;
                *(float2*)(Xre + off) = ore;
                *(float2*)(Xim + off) = oim;
            }
        }
    }

    // ffma epilogue: stored col pl holds true col 128+unperm(pl)
    if (nf_act) {
        #pragma unroll
        for (int rr = 0; rr < 4; rr++) {
            int r = m0 + fr0 + 4 * rg + rr;
            #pragma unroll
            for (int cc = 0; cc < 4; cc++) {
                int pl = 4 * cg + cc;
                int co = 128 + unperm(pl);            // true col offset
                int c  = n0 + co;
                size_t off = (size_t)r * HID + c;
                float sr = Sre[off], si = Sim[off];
                float lr = sLr[co], li = sLi[co], gg = sG[co];
                float tr = accf[0][rr][cc], ti = accf[1][rr][cc];
                Xre[off] = sr * lr - si * li + gg * tr;
                Xim[off] = sr * li + si * lr + gg * ti;
            }
        }
    }
}

// =============================================================================
// GEMM2: Y = [Xre|Xim] @ [Cre'; -Cim'] + D*U (K=4096). Block: 128M x (128t+32f)N
// =============================================================================
__global__ __launch_bounds__(256, 1) void lru_g2(
    const float* __restrict__ Xre, const float* __restrict__ Xim,
    const float* __restrict__ Cp,
    const float* __restrict__ Dv,  const float* __restrict__ U,
    float* __restrict__ Y)
{
    const int n0 = blockIdx.x * 160;     // NREC
    const int m0 = blockIdx.y * 128;     // BATCH
    const bool nf_act = (n0 + 160 <= NREC);
    const bool full_t = (n0 + 128 <= NREC);

    const int tid = threadIdx.x, warp = tid >> 5, lane = tid & 31;
    const int g = lane >> 2, t = lane & 3;
    const int wm = (warp >> 2) * 64, wn = (warp & 3) * 32;
    const int fr0 = warp * 16, rg = lane >> 3, cg = lane & 7;

    float acc[4][4][4];
    float accf[4][4];
    #pragma unroll
    for (int i = 0; i < 4; i++)
        #pragma unroll
        for (int j = 0; j < 4; j++) {
            #pragma unroll
            for (int r = 0; r < 4; r++) acc[i][j][r] = 0.f;
            accf[i][j] = 0.f;
        }

    auto loadStage = [&](int s, int k0) {
        float* a = smem + s * ST2;
        float* b = a + A_TILE;
        float* f = b + B_TILE;
        const float* Asrc = (k0 < HID) ? Xre : Xim;
        const int ka = k0 & (HID - 1);
        #pragma unroll
        for (int i = 0; i < 4; i++) {
            int c = tid + i * 256;
            int row = c >> 3, cc = (c & 7) * 4;
            cp16(a + row * SA + cc, Asrc + (size_t)(m0 + row) * HID + ka + cc);
        }
        #pragma unroll
        for (int i = 0; i < 4; i++) {
            int c = tid + i * 256;
            int row = c >> 5, cc = (c & 31) * 4;
            if (full_t || n0 + cc < NREC)
                cp16(b + row * SB + cc, Cp + (size_t)(k0 + row) * NREC + n0 + cc);
        }
        if (nf_act) {
            int row = tid >> 3, cc = (tid & 7) * 4;
            cp16(f + row * SF + cc, Cp + (size_t)(k0 + row) * NREC + n0 + 128 + cc);
        }
    };

    const int NKT = (2 * HID) / BK;    // 128
    loadStage(0, 0); cp_commit();
    loadStage(1, BK); cp_commit();

    for (int kt = 0; kt < NKT; kt++) {
        if (kt + 2 < NKT) cp_wait1(); else cp_wait0();
        __syncthreads();
        if (kt + 2 < NKT) { loadStage((kt + 2) % 3, (kt + 2) * BK); cp_commit(); }

        const int s = kt % 3;
        const uint32_t* a = (const uint32_t*)(smem + s * ST2);
        const uint32_t* b = a + A_TILE;
        const float* fA = (const float*)a;
        const float* fF = (const float*)(b + B_TILE);

        #pragma unroll
        for (int ks = 0; ks < 4; ks++) {
            const int kk = ks * 8;
            uint32_t af[4][4];
            #pragma unroll
            for (int i = 0; i < 4; i++) {
                int r = wm + i * 16 + g;
                af[i][0] = a[r * SA + kk + t];
                af[i][1] = a[(r + 8) * SA + kk + t];
                af[i][2] = a[r * SA + kk + t + 4];
                af[i][3] = a[(r + 8) * SA + kk + t + 4];
            }
            uint4 v0 = *(const uint4*)(b + (kk + t) * SB + wn + 4 * g);
            uint4 v1 = *(const uint4*)(b + (kk + t + 4) * SB + wn + 4 * g);
            uint32_t b0[4] = {v0.x, v0.y, v0.z, v0.w};
            uint32_t b1[4] = {v1.x, v1.y, v1.z, v1.w};
            #pragma unroll
            for (int i = 0; i < 4; i++) {
                #pragma unroll
                for (int j = 0; j < 4; j++)
                    mma8(acc[i][j], af[i], b0[j], b1[j]);
                // 8 FFMA chunks per ktile
                if (((ks * 4 + i) & 1) == 0) {
                    const int kc = (ks * 4 + i) >> 1;
                    float av[4][4], bv[4][4];
                    #pragma unroll
                    for (int rr = 0; rr < 4; rr++) {
                        float4 q = *(const float4*)(fA + (fr0 + 4 * rg + rr) * SA + kc * 4);
                        av[rr][0] = q.x; av[rr][1] = q.y; av[rr][2] = q.z; av[rr][3] = q.w;
                    }
                    #pragma unroll
                    for (int k3 = 0; k3 < 4; k3++) {
                        float4 q = *(const float4*)(fF + (kc * 4 + k3) * SF + 4 * cg);
                        bv[k3][0] = q.x; bv[k3][1] = q.y; bv[k3][2] = q.z; bv[k3][3] = q.w;
                    }
                    #pragma unroll
                    for (int k3 = 0; k3 < 4; k3++)
                        #pragma unroll
                        for (int rr = 0; rr < 4; rr++)
                            #pragma unroll
                            for (int cc = 0; cc < 4; cc++)
                                accf[rr][cc] += av[rr][k3] * bv[k3][cc];
                }
            }
        }
    }

    // tensor epilogue: direct columns, contiguous pairs; guard ragged tail
    #pragma unroll
    for (int i = 0; i < 4; i++) {
        int r0 = m0 + wm + i * 16 + g;
        #pragma unroll
        for (int j = 0; j < 4; j++) {
            int cl = wn + j * 8 + 2 * t;
            int c  = n0 + cl;
            if (c < NREC) {
                float d0 = Dv[c], d1 = Dv[c + 1];
                #pragma unroll
                for (int rr = 0; rr < 2; rr++) {
                    int r = r0 + rr * 8;
                    size_t off = (size_t)r * NREC + c;
                    float2 u = *(const float2*)(U + off);
                    float2 o;
                    o.x = acc[i][j][rr * 2 + 0] + d0 * u.x;
                    o.y = acc[i][j][rr * 2 + 1] + d1 * u.y;
                    *(float2*)(Y + off) = o;
                }
            }
        }
    }

    // ffma epilogue: stored col pl holds true col 128+unperm(pl)
    if (nf_act) {
        #pragma unroll
        for (int rr = 0; rr < 4; rr++) {
            int r = m0 + fr0 + 4 * rg + rr;
            #pragma unroll
            for (int cc = 0; cc < 4; cc++) {
                int pl = 4 * cg + cc;
                int c  = n0 + 128 + unperm(pl);
                size_t off = (size_t)r * NREC + c;
                Y[off] = accf[rr][cc] + Dv[c] * U[off];
            }
        }
    }
}

// =============================================================================
extern "C" void kernel_launch(void* const* d_in, const int* in_sizes, int n_in,
                              void* d_out, int out_size)
{
    const float* U   = (const float*)d_in[0];
    const float* Sre = (const float*)d_in[1];
    const float* Sim = (const float*)d_in[2];
    const float* Bre = (const float*)d_in[3];
    const float* Bim = (const float*)d_in[4];
    const float* Cre = (const float*)d_in[5];
    const float* Cim = (const float*)d_in[6];
    const float* Dv  = (const float*)d_in[7];
    const float* nu  = (const float*)d_in[8];
    const float* th  = (const float*)d_in[9];
    const float* gm  = (const float*)d_in[10];

    float* Y   = (float*)d_out;
    float* Xre = Y + (size_t)BATCH * NREC;
    float* Xim = Xre + (size_t)BATCH * HID;

    float *Bp = nullptr, *Cp = nullptr;
    cudaGetSymbolAddress((void**)&Bp, g_B);
    cudaGetSymbolAddress((void**)&Cp, g_C);

    const int tot = NREC * HID;
    dim3 gp(tot / 256, 4);
    prep_all<<<gp, 256>>>(Bre, Bim, Cre, Cim, Bp, Cp);

    cudaFuncSetAttribute(lru_g1, cudaFuncAttributeMaxDynamicSharedMemorySize, SMEM1);
    cudaFuncSetAttribute(lru_g2, cudaFuncAttributeMaxDynamicSharedMemorySize, SMEM2);

    dim3 g1((HID + 159) / 160, BATCH / 128);   // 13 x 64
    lru_g1<<<g1, 256, SMEM1>>>(U, Bp, Sre, Sim, nu, th, gm, Xre, Xim);

    dim3 g2((NREC + 159) / 160, BATCH / 128);  // 7 x 64
    lru_g2<<<g2, 256, SMEM2>>>(Xre, Xim, Cp, Dv, U, Y);
}

// round 8
// speedup vs baseline: 2.2529x; 2.2529x over previous
#include <cuda_runtime.h>
#include <cuda_fp16.h>
#include <cstdint>
#include <cstddef>

#define BATCH 8192
#define NREC  1024
#define HID   2048

// All tiles operate on u32 = half2 (k-pair packed) words.
// k-tile = 32 u32 = 64 halfs of K per iteration; 4 mma k16-steps per tile.
#define SA 36       // A smem row stride (u32)
#define SB 136      // B smem row stride (u32)
#define A_TILE (128 * SA)    // 4608 u32
#define B_TILE (32 * SB)     // 4352 u32

// GEMM1 stage: A + Bre + Bim
#define ST1 (A_TILE + 2 * B_TILE)                 // 13312 u32
#define SMEM1 (3 * ST1 * (int)sizeof(uint32_t))   // 159744
// GEMM2 stage: A + B
#define ST2 (A_TILE + B_TILE)                     // 8960 u32
#define SMEM2 (3 * ST2 * (int)sizeof(uint32_t))   // 107520

extern __shared__ uint32_t smem[];

// ---- packed scratch (half2 words) ----
__device__ uint32_t g_PU[(size_t)BATCH * (NREC / 2)];        // U packed along k
__device__ uint32_t g_PB[2u * (NREC / 2) * HID];             // [Bre|Bim], [k2][n] n-permuted
__device__ uint32_t g_PC[(size_t)HID * NREC];                // [Cre;-Cim] stacked, [k2=2048][n] n-permuted
__device__ uint32_t g_PXre[(size_t)BATCH * (HID / 2)];       // X packed along h
__device__ uint32_t g_PXim[(size_t)BATCH * (HID / 2)];

__device__ __forceinline__ void mma16(float* d, const uint32_t* a, uint32_t b0, uint32_t b1) {
    asm volatile(
        "mma.sync.aligned.m16n8k16.row.col.f32.f16.f16.f32 "
        "{%0,%1,%2,%3}, {%4,%5,%6,%7}, {%8,%9}, {%0,%1,%2,%3};\n"
        : "+f"(d[0]), "+f"(d[1]), "+f"(d[2]), "+f"(d[3])
        : "r"(a[0]), "r"(a[1]), "r"(a[2]), "r"(a[3]), "r"(b0), "r"(b1));
}
__device__ __forceinline__ void cp16(void* s, const void* g) {
    uint32_t sa = (uint32_t)__cvta_generic_to_shared(s);
    asm volatile("cp.async.cg.shared.global [%0], [%1], 16;\n" :: "r"(sa), "l"(g));
}
__device__ __forceinline__ void cp_commit() { asm volatile("cp.async.commit_group;\n"); }
__device__ __forceinline__ void cp_wait0()  { asm volatile("cp.async.wait_group 0;\n"); }
__device__ __forceinline__ void cp_wait1()  { asm volatile("cp.async.wait_group 1;\n"); }

__device__ __forceinline__ uint32_t packh2(float x, float y) {
    __half2 h = __floats2half2_rn(x, y);
    return *(uint32_t*)&h;
}

// ---- prep weights: pack k-pairs into half2, permute n within 32-blocks, negate Cim.
// stored col (base+p) holds source col (base + (p&3)*8 + (p>>2)) — makes LDS.128
// deliver mma-b fragments directly; accumulator local col == true col (direct epilogue).
__global__ __launch_bounds__(256) void prep_w(
    const float* __restrict__ B0, const float* __restrict__ B1,
    const float* __restrict__ C0, const float* __restrict__ C1,
    uint32_t* __restrict__ PB, uint32_t* __restrict__ PC)
{
    const int idx = blockIdx.x * 256 + threadIdx.x;   // over 512*2048 = 1024*1024 words
    const int z = blockIdx.y;
    const float* src; uint32_t* dst; int sh; float sign = 1.f;
    if (z == 0)      { src = B0; dst = PB;                          sh = 11; }  // N=2048
    else if (z == 1) { src = B1; dst = PB + (NREC / 2) * HID;       sh = 11; }
    else if (z == 2) { src = C0; dst = PC;                          sh = 10; }  // N=1024
    else             { src = C1; dst = PC + (size_t)(HID / 2) * NREC; sh = 10; sign = -1.f; }
    const int N = 1 << sh;
    const int k2 = idx >> sh, l = idx & (N - 1);
    const int base = l & ~31, p = l & 31;
    const int nt = base + ((p & 3) * 8) + (p >> 2);
    float v0 = sign * src[((size_t)(2 * k2) << sh) + nt];
    float v1 = sign * src[((size_t)(2 * k2 + 1) << sh) + nt];
    dst[idx] = packh2(v0, v1);
}

// ---- prep U: pack adjacent k-pairs (natural order) ----
__global__ __launch_bounds__(256) void prep_u(const float* __restrict__ U,
                                              uint32_t* __restrict__ PU)
{
    const int idx = blockIdx.x * 256 + threadIdx.x;   // over 8192*512
    const float2 v = *(const float2*)(U + 2 * (size_t)idx);
    PU[idx] = packh2(v.x, v.y);
}

// =============================================================================
// GEMM1 (fused): Tre = U @ Bre, Tim = U @ Bim; X = f(S,T); also emit packed X.
// block 128x128, 256 thr, 8 warps (2M x 4N), warp 64x32 per matrix, 3 stages
// =============================================================================
__global__ __launch_bounds__(256, 1) void lru_g1(
    const uint32_t* __restrict__ PU,
    const uint32_t* __restrict__ PB,
    const float* __restrict__ Sre, const float* __restrict__ Sim,
    const float* __restrict__ nu,  const float* __restrict__ theta,
    const float* __restrict__ gam,
    float* __restrict__ Xre, float* __restrict__ Xim,
    uint32_t* __restrict__ PXre, uint32_t* __restrict__ PXim)
{
    const int n0 = blockIdx.x * 128;     // HID
    const int m0 = blockIdx.y * 128;     // BATCH
    const uint32_t* __restrict__ Bre = PB;
    const uint32_t* __restrict__ Bim = PB + (NREC / 2) * HID;

    const int tid = threadIdx.x, warp = tid >> 5, lane = tid & 31;
    const int g = lane >> 2, t = lane & 3;
    const int wm = (warp >> 2) * 64, wn = (warp & 3) * 32;

    float ar[4][4][4], ai[4][4][4];
    #pragma unroll
    for (int i = 0; i < 4; i++)
        #pragma unroll
        for (int j = 0; j < 4; j++)
            #pragma unroll
            for (int r = 0; r < 4; r++) { ar[i][j][r] = 0.f; ai[i][j][r] = 0.f; }

    // k-tile kt covers u32 cols [kt*32, kt*32+32) of PU (= 64 halfs of K)
    auto loadStage = [&](int s, int kt) {
        uint32_t* a  = smem + s * ST1;
        uint32_t* br = a + A_TILE;
        uint32_t* bi = br + B_TILE;
        const int k2 = kt * 32;
        #pragma unroll
        for (int i = 0; i < 4; i++) {
            int c = tid + i * 256;                 // 1024 chunks: 128 rows x 8
            int row = c >> 3, cc = (c & 7) * 4;
            cp16(a + row * SA + cc, PU + (size_t)(m0 + row) * (NREC / 2) + k2 + cc);
        }
        #pragma unroll
        for (int i = 0; i < 4; i++) {
            int c = tid + i * 256;                 // 1024 chunks: 32 k2-rows x 32
            int row = c >> 5, cc = (c & 31) * 4;
            size_t go = (size_t)(k2 + row) * HID + n0 + cc;
            cp16(br + row * SB + cc, Bre + go);
            cp16(bi + row * SB + cc, Bim + go);
        }
    };

    const int NKT = (NREC / 2) / 32;   // 16
    loadStage(0, 0); cp_commit();
    loadStage(1, 1); cp_commit();

    for (int kt = 0; kt < NKT; kt++) {
        if (kt + 2 < NKT) cp_wait1(); else cp_wait0();
        __syncthreads();
        if (kt + 2 < NKT) { loadStage((kt + 2) % 3, kt + 2); cp_commit(); }

        const int s = kt % 3;
        const uint32_t* a  = smem + s * ST1;
        const uint32_t* br = a + A_TILE;
        const uint32_t* bi = br + B_TILE;
        #pragma unroll
        for (int ks = 0; ks < 4; ks++) {          // 4 x k16
            const int kk = ks * 8;
            uint32_t af[4][4];
            #pragma unroll
            for (int i = 0; i < 4; i++) {
                int r = wm + i * 16 + g;
                af[i][0] = a[r * SA + kk + t];
                af[i][1] = a[(r + 8) * SA + kk + t];
                af[i][2] = a[r * SA + kk + t + 4];
                af[i][3] = a[(r + 8) * SA + kk + t + 4];
            }
            uint4 v0 = *(const uint4*)(br + (kk + t) * SB + wn + 4 * g);
            uint4 v1 = *(const uint4*)(br + (kk + t + 4) * SB + wn + 4 * g);
            uint4 w0 = *(const uint4*)(bi + (kk + t) * SB + wn + 4 * g);
            uint4 w1 = *(const uint4*)(bi + (kk + t + 4) * SB + wn + 4 * g);
            uint32_t b0[4] = {v0.x, v0.y, v0.z, v0.w};
            uint32_t b1[4] = {v1.x, v1.y, v1.z, v1.w};
            uint32_t c0[4] = {w0.x, w0.y, w0.z, w0.w};
            uint32_t c1[4] = {w1.x, w1.y, w1.z, w1.w};
            #pragma unroll
            for (int i = 0; i < 4; i++)
                #pragma unroll
                for (int j = 0; j < 4; j++) {
                    mma16(ar[i][j], af[i], b0[j], b1[j]);
                    mma16(ai[i][j], af[i], c0[j], c1[j]);
                }
        }
    }

    // lambda/gamma tables for this block's 128 true H-columns
    float* sLr = (float*)smem;
    float* sLi = sLr + 128;
    float* sG  = sLr + 256;
    __syncthreads();
    if (tid < 128) {
        int h = n0 + tid;
        float e = expf(-expf(nu[h]));
        float th = theta[h];
        sLr[tid] = e * cosf(th);
        sLi[tid] = e * sinf(th);
        sG[tid]  = gam[h];
    }
    __syncthreads();

    // epilogue: acc local col cl IS true col n0+cl (direct); write fp32 X and packed X
    #pragma unroll
    for (int i = 0; i < 4; i++) {
        int r0 = m0 + wm + i * 16 + g;
        #pragma unroll
        for (int j = 0; j < 4; j++) {
            int cl = wn + j * 8 + 2 * t;
            float lr0 = sLr[cl],     li0 = sLi[cl],     g0 = sG[cl];
            float lr1 = sLr[cl + 1], li1 = sLi[cl + 1], g1 = sG[cl + 1];
            #pragma unroll
            for (int rr = 0; rr < 2; rr++) {
                int r = r0 + rr * 8;
                size_t off = (size_t)r * HID + n0 + cl;
                float2 sre = *(const float2*)(Sre + off);
                float2 sim = *(const float2*)(Sim + off);
                float tr0 = ar[i][j][rr * 2 + 0], tr1 = ar[i][j][rr * 2 + 1];
                float ti0 = ai[i][j][rr * 2 + 0], ti1 = ai[i][j][rr * 2 + 1];
                float2 ore, oim;
                ore.x = sre.x * lr0 - sim.x * li0 + g0 * tr0;
                ore.y = sre.y * lr1 - sim.y * li1 + g1 * tr1;
                oim.x = sre.x * li0 + sim.x * lr0 + g0 * ti0;
                oim.y = sre.y * li1 + sim.y * lr1 + g1 * ti1;
                *(float2*)(Xre + off) = ore;
                *(float2*)(Xim + off) = oim;
                size_t poff = (size_t)r * (HID / 2) + (n0 + cl) / 2;
                PXre[poff] = packh2(ore.x, ore.y);
                PXim[poff] = packh2(oim.x, oim.y);
            }
        }
    }
}

// =============================================================================
// GEMM2: Y = [Xre|Xim] @ [Cre;-Cim] + D*U   (K = 4096 halfs = 2048 u32)
// block 128x128, 256 thr, warp 64x32, 3 stages
// =============================================================================
__global__ __launch_bounds__(256, 1) void lru_g2(
    const uint32_t* __restrict__ PXre, const uint32_t* __restrict__ PXim,
    const uint32_t* __restrict__ PC,
    const float* __restrict__ Dv,  const float* __restrict__ U,
    float* __restrict__ Y)
{
    const int n0 = blockIdx.x * 128;     // NREC
    const int m0 = blockIdx.y * 128;     // BATCH
    const int tid = threadIdx.x, warp = tid >> 5, lane = tid & 31;
    const int g = lane >> 2, t = lane & 3;
    const int wm = (warp >> 2) * 64, wn = (warp & 3) * 32;

    float acc[4][4][4];
    #pragma unroll
    for (int i = 0; i < 4; i++)
        #pragma unroll
        for (int j = 0; j < 4; j++)
            #pragma unroll
            for (int r = 0; r < 4; r++) acc[i][j][r] = 0.f;

    auto loadStage = [&](int s, int kt) {
        uint32_t* a = smem + s * ST2;
        uint32_t* b = a + A_TILE;
        const int k2 = kt * 32;                       // u32 index within 2048
        const uint32_t* Asrc = (k2 < HID / 2) ? PXre : PXim;
        const int ka = k2 & (HID / 2 - 1);
        #pragma unroll
        for (int i = 0; i < 4; i++) {
            int c = tid + i * 256;
            int row = c >> 3, cc = (c & 7) * 4;
            cp16(a + row * SA + cc, Asrc + (size_t)(m0 + row) * (HID / 2) + ka + cc);
        }
        #pragma unroll
        for (int i = 0; i < 4; i++) {
            int c = tid + i * 256;
            int row = c >> 5, cc = (c & 31) * 4;
            cp16(b + row * SB + cc, PC + (size_t)(k2 + row) * NREC + n0 + cc);
        }
    };

    const int NKT = 2048 / 32;    // 64
    loadStage(0, 0); cp_commit();
    loadStage(1, 1); cp_commit();

    for (int kt = 0; kt < NKT; kt++) {
        if (kt + 2 < NKT) cp_wait1(); else cp_wait0();
        __syncthreads();
        if (kt + 2 < NKT) { loadStage((kt + 2) % 3, kt + 2); cp_commit(); }

        const int s = kt % 3;
        const uint32_t* a = smem + s * ST2;
        const uint32_t* b = a + A_TILE;
        #pragma unroll
        for (int ks = 0; ks < 4; ks++) {
            const int kk = ks * 8;
            uint32_t af[4][4];
            #pragma unroll
            for (int i = 0; i < 4; i++) {
                int r = wm + i * 16 + g;
                af[i][0] = a[r * SA + kk + t];
                af[i][1] = a[(r + 8) * SA + kk + t];
                af[i][2] = a[r * SA + kk + t + 4];
                af[i][3] = a[(r + 8) * SA + kk + t + 4];
            }
            uint4 v0 = *(const uint4*)(b + (kk + t) * SB + wn + 4 * g);
            uint4 v1 = *(const uint4*)(b + (kk + t + 4) * SB + wn + 4 * g);
            uint32_t b0[4] = {v0.x, v0.y, v0.z, v0.w};
            uint32_t b1[4] = {v1.x, v1.y, v1.z, v1.w};
            #pragma unroll
            for (int i = 0; i < 4; i++)
                #pragma unroll
                for (int j = 0; j < 4; j++)
                    mma16(acc[i][j], af[i], b0[j], b1[j]);
        }
    }

    // epilogue: y = acc + D[c]*U[r,c]  (direct columns)
    #pragma unroll
    for (int i = 0; i < 4; i++) {
        int r0 = m0 + wm + i * 16 + g;
        #pragma unroll
        for (int j = 0; j < 4; j++) {
            int cl = wn + j * 8 + 2 * t;
            int c  = n0 + cl;
            float d0 = Dv[c], d1 = Dv[c + 1];
            #pragma unroll
            for (int rr = 0; rr < 2; rr++) {
                int r = r0 + rr * 8;
                size_t off = (size_t)r * NREC + c;
                float2 u = *(const float2*)(U + off);
                float2 o;
                o.x = acc[i][j][rr * 2 + 0] + d0 * u.x;
                o.y = acc[i][j][rr * 2 + 1] + d1 * u.y;
                *(float2*)(Y + off) = o;
            }
        }
    }
}

// =============================================================================
extern "C" void kernel_launch(void* const* d_in, const int* in_sizes, int n_in,
                              void* d_out, int out_size)
{
    const float* U   = (const float*)d_in[0];
    const float* Sre = (const float*)d_in[1];
    const float* Sim = (const float*)d_in[2];
    const float* Bre = (const float*)d_in[3];
    const float* Bim = (const float*)d_in[4];
    const float* Cre = (const float*)d_in[5];
    const float* Cim = (const float*)d_in[6];
    const float* Dv  = (const float*)d_in[7];
    const float* nu  = (const float*)d_in[8];
    const float* th  = (const float*)d_in[9];
    const float* gm  = (const float*)d_in[10];

    float* Y   = (float*)d_out;
    float* Xre = Y + (size_t)BATCH * NREC;
    float* Xim = Xre + (size_t)BATCH * HID;

    uint32_t *PU, *PB, *PC, *PXre, *PXim;
    cudaGetSymbolAddress((void**)&PU, g_PU);
    cudaGetSymbolAddress((void**)&PB, g_PB);
    cudaGetSymbolAddress((void**)&PC, g_PC);
    cudaGetSymbolAddress((void**)&PXre, g_PXre);
    cudaGetSymbolAddress((void**)&PXim, g_PXim);

    // prep: weights (4 x 1M words) and U (4M words)
    dim3 gw((NREC / 2) * HID / 256, 4);              // 4096 x 4
    prep_w<<<gw, 256>>>(Bre, Bim, Cre, Cim, PB, PC);
    prep_u<<<BATCH * (NREC / 2) / 256, 256>>>(U, PU);

    cudaFuncSetAttribute(lru_g1, cudaFuncAttributeMaxDynamicSharedMemorySize, SMEM1);
    cudaFuncSetAttribute(lru_g2, cudaFuncAttributeMaxDynamicSharedMemorySize, SMEM2);

    dim3 g1(HID / 128, BATCH / 128);     // 16 x 64
    lru_g1<<<g1, 256, SMEM1>>>(PU, PB, Sre, Sim, nu, th, gm, Xre, Xim, PXre, PXim);

    dim3 g2(NREC / 128, BATCH / 128);    // 8 x 64
    lru_g2<<<g2, 256, SMEM2>>>(PXre, PXim, PC, Dv, U, Y);
}

// round 9
// speedup vs baseline: 2.3126x; 1.0265x over previous
#include <cuda_runtime.h>
#include <cuda_fp16.h>
#include <cstdint>
#include <cstddef>

#define BATCH 8192
#define NREC  1024
#define HID   2048

// All tiles operate on u32 = half2 (k-pair packed) words.
#define SA 36       // A smem row stride (u32)
#define SB 136      // B smem row stride (u32)
#define A_TILE (128 * SA)    // 4608 u32
#define B_TILE (32 * SB)     // 4352 u32
#define ST (A_TILE + B_TILE) // 8960 u32 per stage
#define SMEM_B (3 * ST * (int)sizeof(uint32_t))    // 107520 -> 2 CTAs/SM

extern __shared__ uint32_t smem[];

// ---- packed scratch (half2 words) ----
__device__ uint32_t g_PU[(size_t)BATCH * (NREC / 2)];
__device__ uint32_t g_PB[2u * (NREC / 2) * HID];             // [Bre|Bim], [k2][n] n-permuted
__device__ uint32_t g_PC[(size_t)HID * NREC];                // [Cre;-Cim], [k2=2048][n] n-permuted
__device__ uint32_t g_PXre[(size_t)BATCH * (HID / 2)];
__device__ uint32_t g_PXim[(size_t)BATCH * (HID / 2)];

__device__ __forceinline__ void mma16(float* d, const uint32_t* a, uint32_t b0, uint32_t b1) {
    asm volatile(
        "mma.sync.aligned.m16n8k16.row.col.f32.f16.f16.f32 "
        "{%0,%1,%2,%3}, {%4,%5,%6,%7}, {%8,%9}, {%0,%1,%2,%3};\n"
        : "+f"(d[0]), "+f"(d[1]), "+f"(d[2]), "+f"(d[3])
        : "r"(a[0]), "r"(a[1]), "r"(a[2]), "r"(a[3]), "r"(b0), "r"(b1));
}
__device__ __forceinline__ void cp16(void* s, const void* g) {
    uint32_t sa = (uint32_t)__cvta_generic_to_shared(s);
    asm volatile("cp.async.cg.shared.global [%0], [%1], 16;\n" :: "r"(sa), "l"(g));
}
__device__ __forceinline__ void cp_commit() { asm volatile("cp.async.commit_group;\n"); }
__device__ __forceinline__ void cp_wait0()  { asm volatile("cp.async.wait_group 0;\n"); }
__device__ __forceinline__ void cp_wait1()  { asm volatile("cp.async.wait_group 1;\n"); }

__device__ __forceinline__ uint32_t packh2(float x, float y) {
    __half2 h = __floats2half2_rn(x, y);
    return *(uint32_t*)&h;
}

// ---- prep weights: pack k-pairs into half2, permute n within 32-blocks, negate Cim.
__global__ __launch_bounds__(256) void prep_w(
    const float* __restrict__ B0, const float* __restrict__ B1,
    const float* __restrict__ C0, const float* __restrict__ C1,
    uint32_t* __restrict__ PB, uint32_t* __restrict__ PC)
{
    const int idx = blockIdx.x * 256 + threadIdx.x;
    const int z = blockIdx.y;
    const float* src; uint32_t* dst; int sh; float sign = 1.f;
    if (z == 0)      { src = B0; dst = PB;                            sh = 11; }
    else if (z == 1) { src = B1; dst = PB + (NREC / 2) * HID;         sh = 11; }
    else if (z == 2) { src = C0; dst = PC;                            sh = 10; }
    else             { src = C1; dst = PC + (size_t)(HID / 2) * NREC; sh = 10; sign = -1.f; }
    const int N = 1 << sh;
    const int k2 = idx >> sh, l = idx & (N - 1);
    const int base = l & ~31, p = l & 31;
    const int nt = base + ((p & 3) * 8) + (p >> 2);
    float v0 = sign * src[((size_t)(2 * k2) << sh) + nt];
    float v1 = sign * src[((size_t)(2 * k2 + 1) << sh) + nt];
    dst[idx] = packh2(v0, v1);
}

__global__ __launch_bounds__(256) void prep_u(const float* __restrict__ U,
                                              uint32_t* __restrict__ PU)
{
    const int idx = blockIdx.x * 256 + threadIdx.x;
    const float2 v = *(const float2*)(U + 2 * (size_t)idx);
    PU[idx] = packh2(v.x, v.y);
}

// =============================================================================
// GEMM1: T = U @ B{re|im} (z selects); X{re|im} = f(S, T); emits fp32 + packed X.
// block 128x128, 256 thr, warp 64x32, 3 stages, 2 CTAs/SM
// =============================================================================
__global__ __launch_bounds__(256, 2) void lru_g1(
    const uint32_t* __restrict__ PU,
    const uint32_t* __restrict__ PB,
    const float* __restrict__ Sre, const float* __restrict__ Sim,
    const float* __restrict__ nu,  const float* __restrict__ theta,
    const float* __restrict__ gam,
    float* __restrict__ Xre, float* __restrict__ Xim,
    uint32_t* __restrict__ PXre, uint32_t* __restrict__ PXim)
{
    const int n0 = blockIdx.x * 128;     // HID
    const int m0 = blockIdx.y * 128;     // BATCH
    const int z  = blockIdx.z;
    const uint32_t* __restrict__ Bmat = PB + (size_t)z * (NREC / 2) * HID;

    const int tid = threadIdx.x, warp = tid >> 5, lane = tid & 31;
    const int g = lane >> 2, t = lane & 3;
    const int wm = (warp >> 2) * 64, wn = (warp & 3) * 32;

    float acc[4][4][4];
    #pragma unroll
    for (int i = 0; i < 4; i++)
        #pragma unroll
        for (int j = 0; j < 4; j++)
            #pragma unroll
            for (int r = 0; r < 4; r++) acc[i][j][r] = 0.f;

    auto loadStage = [&](int s, int kt) {
        uint32_t* a = smem + s * ST;
        uint32_t* b = a + A_TILE;
        const int k2 = kt * 32;
        #pragma unroll
        for (int i = 0; i < 4; i++) {
            int c = tid + i * 256;
            int row = c >> 3, cc = (c & 7) * 4;
            cp16(a + row * SA + cc, PU + (size_t)(m0 + row) * (NREC / 2) + k2 + cc);
        }
        #pragma unroll
        for (int i = 0; i < 4; i++) {
            int c = tid + i * 256;
            int row = c >> 5, cc = (c & 31) * 4;
            cp16(b + row * SB + cc, Bmat + (size_t)(k2 + row) * HID + n0 + cc);
        }
    };

    const int NKT = (NREC / 2) / 32;   // 16
    loadStage(0, 0); cp_commit();
    loadStage(1, 1); cp_commit();

    for (int kt = 0; kt < NKT; kt++) {
        if (kt + 2 < NKT) cp_wait1(); else cp_wait0();
        __syncthreads();
        if (kt + 2 < NKT) { loadStage((kt + 2) % 3, kt + 2); cp_commit(); }

        const int s = kt % 3;
        const uint32_t* a = smem + s * ST;
        const uint32_t* b = a + A_TILE;
        #pragma unroll
        for (int ks = 0; ks < 4; ks++) {
            const int kk = ks * 8;
            uint32_t af[4][4];
            #pragma unroll
            for (int i = 0; i < 4; i++) {
                int r = wm + i * 16 + g;
                af[i][0] = a[r * SA + kk + t];
                af[i][1] = a[(r + 8) * SA + kk + t];
                af[i][2] = a[r * SA + kk + t + 4];
                af[i][3] = a[(r + 8) * SA + kk + t + 4];
            }
            uint4 v0 = *(const uint4*)(b + (kk + t) * SB + wn + 4 * g);
            uint4 v1 = *(const uint4*)(b + (kk + t + 4) * SB + wn + 4 * g);
            uint32_t b0[4] = {v0.x, v0.y, v0.z, v0.w};
            uint32_t b1[4] = {v1.x, v1.y, v1.z, v1.w};
            #pragma unroll
            for (int i = 0; i < 4; i++)
                #pragma unroll
                for (int j = 0; j < 4; j++)
                    mma16(acc[i][j], af[i], b0[j], b1[j]);
        }
    }

    // lambda/gamma tables for this block's 128 true H-columns
    float* sLr = (float*)smem;
    float* sLi = sLr + 128;
    float* sG  = sLr + 256;
    __syncthreads();
    if (tid < 128) {
        int h = n0 + tid;
        float e = expf(-expf(nu[h]));
        float th = theta[h];
        sLr[tid] = e * cosf(th);
        sLi[tid] = e * sinf(th);
        sG[tid]  = gam[h];
    }
    __syncthreads();

    float* __restrict__ Xout = z ? Xim : Xre;
    uint32_t* __restrict__ PXout = z ? PXim : PXre;
    #pragma unroll
    for (int i = 0; i < 4; i++) {
        int r0 = m0 + wm + i * 16 + g;
        #pragma unroll
        for (int j = 0; j < 4; j++) {
            int cl = wn + j * 8 + 2 * t;
            float lr0 = sLr[cl],     li0 = sLi[cl],     g0 = sG[cl];
            float lr1 = sLr[cl + 1], li1 = sLi[cl + 1], g1 = sG[cl + 1];
            #pragma unroll
            for (int rr = 0; rr < 2; rr++) {
                int r = r0 + rr * 8;
                size_t off = (size_t)r * HID + n0 + cl;
                float2 sre = *(const float2*)(Sre + off);
                float2 sim = *(const float2*)(Sim + off);
                float t0 = acc[i][j][rr * 2 + 0], t1 = acc[i][j][rr * 2 + 1];
                float2 o;
                if (z == 0) {
                    o.x = sre.x * lr0 - sim.x * li0 + g0 * t0;
                    o.y = sre.y * lr1 - sim.y * li1 + g1 * t1;
                } else {
                    o.x = sre.x * li0 + sim.x * lr0 + g0 * t0;
                    o.y = sre.y * li1 + sim.y * lr1 + g1 * t1;
                }
                *(float2*)(Xout + off) = o;
                PXout[(size_t)r * (HID / 2) + (n0 + cl) / 2] = packh2(o.x, o.y);
            }
        }
    }
}

// =============================================================================
// GEMM2: Y = [Xre|Xim] @ [Cre;-Cim] + D*U   (K = 4096 halfs = 2048 u32)
// block 128x128, 256 thr, warp 64x32, 3 stages, 2 CTAs/SM
// =============================================================================
__global__ __launch_bounds__(256, 2) void lru_g2(
    const uint32_t* __restrict__ PXre, const uint32_t* __restrict__ PXim,
    const uint32_t* __restrict__ PC,
    const float* __restrict__ Dv,  const float* __restrict__ U,
    float* __restrict__ Y)
{
    const int n0 = blockIdx.x * 128;     // NREC
    const int m0 = blockIdx.y * 128;     // BATCH
    const int tid = threadIdx.x, warp = tid >> 5, lane = tid & 31;
    const int g = lane >> 2, t = lane & 3;
    const int wm = (warp >> 2) * 64, wn = (warp & 3) * 32;

    float acc[4][4][4];
    #pragma unroll
    for (int i = 0; i < 4; i++)
        #pragma unroll
        for (int j = 0; j < 4; j++)
            #pragma unroll
            for (int r = 0; r < 4; r++) acc[i][j][r] = 0.f;

    auto loadStage = [&](int s, int kt) {
        uint32_t* a = smem + s * ST;
        uint32_t* b = a + A_TILE;
        const int k2 = kt * 32;
        const uint32_t* Asrc = (k2 < HID / 2) ? PXre : PXim;
        const int ka = k2 & (HID / 2 - 1);
        #pragma unroll
        for (int i = 0; i < 4; i++) {
            int c = tid + i * 256;
            int row = c >> 3, cc = (c & 7) * 4;
            cp16(a + row * SA + cc, Asrc + (size_t)(m0 + row) * (HID / 2) + ka + cc);
        }
        #pragma unroll
        for (int i = 0; i < 4; i++) {
            int c = tid + i * 256;
            int row = c >> 5, cc = (c & 31) * 4;
            cp16(b + row * SB + cc, PC + (size_t)(k2 + row) * NREC + n0 + cc);
        }
    };

    const int NKT = 2048 / 32;    // 64
    loadStage(0, 0); cp_commit();
    loadStage(1, 1); cp_commit();

    for (int kt = 0; kt < NKT; kt++) {
        if (kt + 2 < NKT) cp_wait1(); else cp_wait0();
        __syncthreads();
        if (kt + 2 < NKT) { loadStage((kt + 2) % 3, kt + 2); cp_commit(); }

        const int s = kt % 3;
        const uint32_t* a = smem + s * ST;
        const uint32_t* b = a + A_TILE;
        #pragma unroll
        for (int ks = 0; ks < 4; ks++) {
            const int kk = ks * 8;
            uint32_t af[4][4];
            #pragma unroll
            for (int i = 0; i < 4; i++) {
                int r = wm + i * 16 + g;
                af[i][0] = a[r * SA + kk + t];
                af[i][1] = a[(r + 8) * SA + kk + t];
                af[i][2] = a[r * SA + kk + t + 4];
                af[i][3] = a[(r + 8) * SA + kk + t + 4];
            }
            uint4 v0 = *(const uint4*)(b + (kk + t) * SB + wn + 4 * g);
            uint4 v1 = *(const uint4*)(b + (kk + t + 4) * SB + wn + 4 * g);
            uint32_t b0[4] = {v0.x, v0.y, v0.z, v0.w};
            uint32_t b1[4] = {v1.x, v1.y, v1.z, v1.w};
            #pragma unroll
            for (int i = 0; i < 4; i++)
                #pragma unroll
                for (int j = 0; j < 4; j++)
                    mma16(acc[i][j], af[i], b0[j], b1[j]);
        }
    }

    #pragma unroll
    for (int i = 0; i < 4; i++) {
        int r0 = m0 + wm + i * 16 + g;
        #pragma unroll
        for (int j = 0; j < 4; j++) {
            int cl = wn + j * 8 + 2 * t;
            int c  = n0 + cl;
            float d0 = Dv[c], d1 = Dv[c + 1];
            #pragma unroll
            for (int rr = 0; rr < 2; rr++) {
                int r = r0 + rr * 8;
                size_t off = (size_t)r * NREC + c;
                float2 u = *(const float2*)(U + off);
                float2 o;
                o.x = acc[i][j][rr * 2 + 0] + d0 * u.x;
                o.y = acc[i][j][rr * 2 + 1] + d1 * u.y;
                *(float2*)(Y + off) = o;
            }
        }
    }
}

// =============================================================================
extern "C" void kernel_launch(void* const* d_in, const int* in_sizes, int n_in,
                              void* d_out, int out_size)
{
    const float* U   = (const float*)d_in[0];
    const float* Sre = (const float*)d_in[1];
    const float* Sim = (const float*)d_in[2];
    const float* Bre = (const float*)d_in[3];
    const float* Bim = (const float*)d_in[4];
    const float* Cre = (const float*)d_in[5];
    const float* Cim = (const float*)d_in[6];
    const float* Dv  = (const float*)d_in[7];
    const float* nu  = (const float*)d_in[8];
    const float* th  = (const float*)d_in[9];
    const float* gm  = (const float*)d_in[10];

    float* Y   = (float*)d_out;
    float* Xre = Y + (size_t)BATCH * NREC;
    float* Xim = Xre + (size_t)BATCH * HID;

    uint32_t *PU, *PB, *PC, *PXre, *PXim;
    cudaGetSymbolAddress((void**)&PU, g_PU);
    cudaGetSymbolAddress((void**)&PB, g_PB);
    cudaGetSymbolAddress((void**)&PC, g_PC);
    cudaGetSymbolAddress((void**)&PXre, g_PXre);
    cudaGetSymbolAddress((void**)&PXim, g_PXim);

    dim3 gw((NREC / 2) * HID / 256, 4);
    prep_w<<<gw, 256>>>(Bre, Bim, Cre, Cim, PB, PC);
    prep_u<<<BATCH * (NREC / 2) / 256, 256>>>(U, PU);

    cudaFuncSetAttribute(lru_g1, cudaFuncAttributeMaxDynamicSharedMemorySize, SMEM_B);
    cudaFuncSetAttribute(lru_g2, cudaFuncAttributeMaxDynamicSharedMemorySize, SMEM_B);

    dim3 g1(HID / 128, BATCH / 128, 2);    // 16 x 64 x 2
    lru_g1<<<g1, 256, SMEM_B>>>(PU, PB, Sre, Sim, nu, th, gm, Xre, Xim, PXre, PXim);

    dim3 g2(NREC / 128, BATCH / 128);      // 8 x 64
    lru_g2<<<g2, 256, SMEM_B>>>(PXre, PXim, PC, Dv, U, Y);
}

// round 10
// speedup vs baseline: 2.4503x; 1.0596x over previous
#include <cuda_runtime.h>
#include <cuda_fp16.h>
#include <cstdint>
#include <cstddef>

#define BATCH 8192
#define NREC  1024
#define HID   2048

// All tiles operate on u32 = half2 (k-pair packed) words.
#define SA 36       // A smem row stride (u32)
#define SB 136      // B smem row stride (u32)
#define A_TILE (128 * SA)    // 4608 u32
#define B_TILE (32 * SB)     // 4352 u32
#define ST (A_TILE + B_TILE) // 8960 u32 per stage
#define SMEM_B (3 * ST * (int)sizeof(uint32_t))    // 107520 -> 2 CTAs/SM

extern __shared__ uint32_t smem[];

// ---- packed scratch (half2 words) ----
__device__ uint32_t g_PU[(size_t)BATCH * (NREC / 2)];
__device__ uint32_t g_PB[2u * (NREC / 2) * HID];             // [Bre|Bim], [k2][n] n-permuted
__device__ uint32_t g_PC[(size_t)HID * NREC];                // [Cre;-Cim], [k2=2048][n] n-permuted
__device__ uint32_t g_PXre[(size_t)BATCH * (HID / 2)];
__device__ uint32_t g_PXim[(size_t)BATCH * (HID / 2)];

__device__ __forceinline__ void mma16(float* d, const uint32_t* a, uint32_t b0, uint32_t b1) {
    asm volatile(
        "mma.sync.aligned.m16n8k16.row.col.f32.f16.f16.f32 "
        "{%0,%1,%2,%3}, {%4,%5,%6,%7}, {%8,%9}, {%0,%1,%2,%3};\n"
        : "+f"(d[0]), "+f"(d[1]), "+f"(d[2]), "+f"(d[3])
        : "r"(a[0]), "r"(a[1]), "r"(a[2]), "r"(a[3]), "r"(b0), "r"(b1));
}
__device__ __forceinline__ void ldsm4(uint32_t* r, uint32_t addr) {
    asm volatile("ldmatrix.sync.aligned.m8n8.x4.shared.b16 {%0,%1,%2,%3}, [%4];"
        : "=r"(r[0]), "=r"(r[1]), "=r"(r[2]), "=r"(r[3]) : "r"(addr));
}
__device__ __forceinline__ void cp16(void* s, const void* g) {
    uint32_t sa = (uint32_t)__cvta_generic_to_shared(s);
    asm volatile("cp.async.cg.shared.global [%0], [%1], 16;\n" :: "r"(sa), "l"(g));
}
__device__ __forceinline__ void cp_commit() { asm volatile("cp.async.commit_group;\n"); }
__device__ __forceinline__ void cp_wait0()  { asm volatile("cp.async.wait_group 0;\n"); }
__device__ __forceinline__ void cp_wait1()  { asm volatile("cp.async.wait_group 1;\n"); }

__device__ __forceinline__ uint32_t packh2(float x, float y) {
    __half2 h = __floats2half2_rn(x, y);
    return *(uint32_t*)&h;
}
__device__ __forceinline__ uint32_t s2u(const void* p) {
    return (uint32_t)__cvta_generic_to_shared(p);
}

// ---- prep weights: pack k-pairs into half2, permute n within 32-blocks, negate Cim.
__global__ __launch_bounds__(256) void prep_w(
    const float* __restrict__ B0, const float* __restrict__ B1,
    const float* __restrict__ C0, const float* __restrict__ C1,
    uint32_t* __restrict__ PB, uint32_t* __restrict__ PC)
{
    const int idx = blockIdx.x * 256 + threadIdx.x;
    const int z = blockIdx.y;
    const float* src; uint32_t* dst; int sh; float sign = 1.f;
    if (z == 0)      { src = B0; dst = PB;                            sh = 11; }
    else if (z == 1) { src = B1; dst = PB + (NREC / 2) * HID;         sh = 11; }
    else if (z == 2) { src = C0; dst = PC;                            sh = 10; }
    else             { src = C1; dst = PC + (size_t)(HID / 2) * NREC; sh = 10; sign = -1.f; }
    const int N = 1 << sh;
    const int k2 = idx >> sh, l = idx & (N - 1);
    const int base = l & ~31, p = l & 31;
    const int nt = base + ((p & 3) * 8) + (p >> 2);
    float v0 = sign * src[((size_t)(2 * k2) << sh) + nt];
    float v1 = sign * src[((size_t)(2 * k2 + 1) << sh) + nt];
    dst[idx] = packh2(v0, v1);
}

__global__ __launch_bounds__(256) void prep_u(const float* __restrict__ U,
                                              uint32_t* __restrict__ PU)
{
    const int idx = blockIdx.x * 256 + threadIdx.x;
    const float2 v = *(const float2*)(U + 2 * (size_t)idx);
    PU[idx] = packh2(v.x, v.y);
}

// =============================================================================
// GEMM1: T = U @ B{re|im} (z selects); X{re|im} = f(S, T); emits fp32 + packed X.
// block 128x128, 256 thr, warp 64x32, 3 stages, 2 CTAs/SM, ldmatrix A-fragments
// =============================================================================
__global__ __launch_bounds__(256, 2) void lru_g1(
    const uint32_t* __restrict__ PU,
    const uint32_t* __restrict__ PB,
    const float* __restrict__ Sre, const float* __restrict__ Sim,
    const float* __restrict__ nu,  const float* __restrict__ theta,
    const float* __restrict__ gam,
    float* __restrict__ Xre, float* __restrict__ Xim,
    uint32_t* __restrict__ PXre, uint32_t* __restrict__ PXim)
{
    const int n0 = blockIdx.x * 128;     // HID
    const int m0 = blockIdx.y * 128;     // BATCH
    const int z  = blockIdx.z;
    const uint32_t* __restrict__ Bmat = PB + (size_t)z * (NREC / 2) * HID;

    const int tid = threadIdx.x, warp = tid >> 5, lane = tid & 31;
    const int g = lane >> 2, t = lane & 3;
    const int wm = (warp >> 2) * 64, wn = (warp & 3) * 32;
    // ldmatrix lane addressing: matrix id m = lane>>3
    const int lm = lane >> 3;
    const int arow = wm + (lm & 1) * 8 + (lane & 7);   // + i*16
    const int acol = (lm >> 1) * 4;                    // + ks*8

    float acc[4][4][4];
    #pragma unroll
    for (int i = 0; i < 4; i++)
        #pragma unroll
        for (int j = 0; j < 4; j++)
            #pragma unroll
            for (int r = 0; r < 4; r++) acc[i][j][r] = 0.f;

    auto loadStage = [&](int s, int kt) {
        uint32_t* a = smem + s * ST;
        uint32_t* b = a + A_TILE;
        const int k2 = kt * 32;
        #pragma unroll
        for (int i = 0; i < 4; i++) {
            int c = tid + i * 256;
            int row = c >> 3, cc = (c & 7) * 4;
            cp16(a + row * SA + cc, PU + (size_t)(m0 + row) * (NREC / 2) + k2 + cc);
        }
        #pragma unroll
        for (int i = 0; i < 4; i++) {
            int c = tid + i * 256;
            int row = c >> 5, cc = (c & 31) * 4;
            cp16(b + row * SB + cc, Bmat + (size_t)(k2 + row) * HID + n0 + cc);
        }
    };

    const int NKT = (NREC / 2) / 32;   // 16
    loadStage(0, 0); cp_commit();
    loadStage(1, 1); cp_commit();

    for (int kt = 0; kt < NKT; kt++) {
        if (kt + 2 < NKT) cp_wait1(); else cp_wait0();
        __syncthreads();
        if (kt + 2 < NKT) { loadStage((kt + 2) % 3, kt + 2); cp_commit(); }

        const int s = kt % 3;
        const uint32_t* a = smem + s * ST;
        const uint32_t* b = a + A_TILE;
        const uint32_t aBase = s2u(a) + (uint32_t)((arow * SA + acol) << 2);
        #pragma unroll
        for (int ks = 0; ks < 4; ks++) {
            const int kk = ks * 8;
            uint32_t af[4][4];
            #pragma unroll
            for (int i = 0; i < 4; i++)
                ldsm4(af[i], aBase + (uint32_t)(((i * 16) * SA + kk) << 2));
            uint4 v0 = *(const uint4*)(b + (kk + t) * SB + wn + 4 * g);
            uint4 v1 = *(const uint4*)(b + (kk + t + 4) * SB + wn + 4 * g);
            uint32_t b0[4] = {v0.x, v0.y, v0.z, v0.w};
            uint32_t b1[4] = {v1.x, v1.y, v1.z, v1.w};
            #pragma unroll
            for (int i = 0; i < 4; i++)
                #pragma unroll
                for (int j = 0; j < 4; j++)
                    mma16(acc[i][j], af[i], b0[j], b1[j]);
        }
    }

    // lambda/gamma tables for this block's 128 true H-columns
    float* sLr = (float*)smem;
    float* sLi = sLr + 128;
    float* sG  = sLr + 256;
    __syncthreads();
    if (tid < 128) {
        int h = n0 + tid;
        float e = expf(-expf(nu[h]));
        float th = theta[h];
        sLr[tid] = e * cosf(th);
        sLi[tid] = e * sinf(th);
        sG[tid]  = gam[h];
    }
    __syncthreads();

    float* __restrict__ Xout = z ? Xim : Xre;
    uint32_t* __restrict__ PXout = z ? PXim : PXre;
    #pragma unroll
    for (int i = 0; i < 4; i++) {
        int r0 = m0 + wm + i * 16 + g;
        #pragma unroll
        for (int j = 0; j < 4; j++) {
            int cl = wn + j * 8 + 2 * t;
            float lr0 = sLr[cl],     li0 = sLi[cl],     g0 = sG[cl];
            float lr1 = sLr[cl + 1], li1 = sLi[cl + 1], g1 = sG[cl + 1];
            #pragma unroll
            for (int rr = 0; rr < 2; rr++) {
                int r = r0 + rr * 8;
                size_t off = (size_t)r * HID + n0 + cl;
                float2 sre = *(const float2*)(Sre + off);
                float2 sim = *(const float2*)(Sim + off);
                float t0 = acc[i][j][rr * 2 + 0], t1 = acc[i][j][rr * 2 + 1];
                float2 o;
                if (z == 0) {
                    o.x = sre.x * lr0 - sim.x * li0 + g0 * t0;
                    o.y = sre.y * lr1 - sim.y * li1 + g1 * t1;
                } else {
                    o.x = sre.x * li0 + sim.x * lr0 + g0 * t0;
                    o.y = sre.y * li1 + sim.y * lr1 + g1 * t1;
                }
                *(float2*)(Xout + off) = o;
                PXout[(size_t)r * (HID / 2) + (n0 + cl) / 2] = packh2(o.x, o.y);
            }
        }
    }
}

// =============================================================================
// GEMM2: Y = [Xre|Xim] @ [Cre;-Cim] + D*U   (K = 4096 halfs = 2048 u32)
// block 128x128, 256 thr, warp 64x32, 3 stages, 2 CTAs/SM, ldmatrix A-fragments
// =============================================================================
__global__ __launch_bounds__(256, 2) void lru_g2(
    const uint32_t* __restrict__ PXre, const uint32_t* __restrict__ PXim,
    const uint32_t* __restrict__ PC,
    const float* __restrict__ Dv,  const float* __restrict__ U,
    float* __restrict__ Y)
{
    const int n0 = blockIdx.x * 128;     // NREC
    const int m0 = blockIdx.y * 128;     // BATCH
    const int tid = threadIdx.x, warp = tid >> 5, lane = tid & 31;
    const int g = lane >> 2, t = lane & 3;
    const int wm = (warp >> 2) * 64, wn = (warp & 3) * 32;
    const int lm = lane >> 3;
    const int arow = wm + (lm & 1) * 8 + (lane & 7);
    const int acol = (lm >> 1) * 4;

    float acc[4][4][4];
    #pragma unroll
    for (int i = 0; i < 4; i++)
        #pragma unroll
        for (int j = 0; j < 4; j++)
            #pragma unroll
            for (int r = 0; r < 4; r++) acc[i][j][r] = 0.f;

    auto loadStage = [&](int s, int kt) {
        uint32_t* a = smem + s * ST;
        uint32_t* b = a + A_TILE;
        const int k2 = kt * 32;
        const uint32_t* Asrc = (k2 < HID / 2) ? PXre : PXim;
        const int ka = k2 & (HID / 2 - 1);
        #pragma unroll
        for (int i = 0; i < 4; i++) {
            int c = tid + i * 256;
            int row = c >> 3, cc = (c & 7) * 4;
            cp16(a + row * SA + cc, Asrc + (size_t)(m0 + row) * (HID / 2) + ka + cc);
        }
        #pragma unroll
        for (int i = 0; i < 4; i++) {
            int c = tid + i * 256;
            int row = c >> 5, cc = (c & 31) * 4;
            cp16(b + row * SB + cc, PC + (size_t)(k2 + row) * NREC + n0 + cc);
        }
    };

    const int NKT = 2048 / 32;    // 64
    loadStage(0, 0); cp_commit();
    loadStage(1, 1); cp_commit();

    for (int kt = 0; kt < NKT; kt++) {
        if (kt + 2 < NKT) cp_wait1(); else cp_wait0();
        __syncthreads();
        if (kt + 2 < NKT) { loadStage((kt + 2) % 3, kt + 2); cp_commit(); }

        const int s = kt % 3;
        const uint32_t* a = smem + s * ST;
        const uint32_t* b = a + A_TILE;
        const uint32_t aBase = s2u(a) + (uint32_t)((arow * SA + acol) << 2);
        #pragma unroll
        for (int ks = 0; ks < 4; ks++) {
            const int kk = ks * 8;
            uint32_t af[4][4];
            #pragma unroll
            for (int i = 0; i < 4; i++)
                ldsm4(af[i], aBase + (uint32_t)(((i * 16) * SA + kk) << 2));
            uint4 v0 = *(const uint4*)(b + (kk + t) * SB + wn + 4 * g);
            uint4 v1 = *(const uint4*)(b + (kk + t + 4) * SB + wn + 4 * g);
            uint32_t b0[4] = {v0.x, v0.y, v0.z, v0.w};
            uint32_t b1[4] = {v1.x, v1.y, v1.z, v1.w};
            #pragma unroll
            for (int i = 0; i < 4; i++)
                #pragma unroll
                for (int j = 0; j < 4; j++)
                    mma16(acc[i][j], af[i], b0[j], b1[j]);
        }
    }

    #pragma unroll
    for (int i = 0; i < 4; i++) {
        int r0 = m0 + wm + i * 16 + g;
        #pragma unroll
        for (int j = 0; j < 4; j++) {
            int cl = wn + j * 8 + 2 * t;
            int c  = n0 + cl;
            float d0 = Dv[c], d1 = Dv[c + 1];
            #pragma unroll
            for (int rr = 0; rr < 2; rr++) {
                int r = r0 + rr * 8;
                size_t off = (size_t)r * NREC + c;
                float2 u = *(const float2*)(U + off);
                float2 o;
                o.x = acc[i][j][rr * 2 + 0] + d0 * u.x;
                o.y = acc[i][j][rr * 2 + 1] + d1 * u.y;
                *(float2*)(Y + off) = o;
            }
        }
    }
}

// =============================================================================
extern "C" void kernel_launch(void* const* d_in, const int* in_sizes, int n_in,
                              void* d_out, int out_size)
{
    const float* U   = (const float*)d_in[0];
    const float* Sre = (const float*)d_in[1];
    const float* Sim = (const float*)d_in[2];
    const float* Bre = (const float*)d_in[3];
    const float* Bim = (const float*)d_in[4];
    const float* Cre = (const float*)d_in[5];
    const float* Cim = (const float*)d_in[6];
    const float* Dv  = (const float*)d_in[7];
    const float* nu  = (const float*)d_in[8];
    const float* th  = (const float*)d_in[9];
    const float* gm  = (const float*)d_in[10];

    float* Y   = (float*)d_out;
    float* Xre = Y + (size_t)BATCH * NREC;
    float* Xim = Xre + (size_t)BATCH * HID;

    uint32_t *PU, *PB, *PC, *PXre, *PXim;
    cudaGetSymbolAddress((void**)&PU, g_PU);
    cudaGetSymbolAddress((void**)&PB, g_PB);
    cudaGetSymbolAddress((void**)&PC, g_PC);
    cudaGetSymbolAddress((void**)&PXre, g_PXre);
    cudaGetSymbolAddress((void**)&PXim, g_PXim);

    dim3 gw((NREC / 2) * HID / 256, 4);
    prep_w<<<gw, 256>>>(Bre, Bim, Cre, Cim, PB, PC);
    prep_u<<<BATCH * (NREC / 2) / 256, 256>>>(U, PU);

    cudaFuncSetAttribute(lru_g1, cudaFuncAttributeMaxDynamicSharedMemorySize, SMEM_B);
    cudaFuncSetAttribute(lru_g2, cudaFuncAttributeMaxDynamicSharedMemorySize, SMEM_B);

    dim3 g1(HID / 128, BATCH / 128, 2);    // 16 x 64 x 2
    lru_g1<<<g1, 256, SMEM_B>>>(PU, PB, Sre, Sim, nu, th, gm, Xre, Xim, PXre, PXim);

    dim3 g2(NREC / 128, BATCH / 128);      // 8 x 64
    lru_g2<<<g2, 256, SMEM_B>>>(PXre, PXim, PC, Dv, U, Y);
}